// round 10
// baseline (speedup 1.0000x reference)
#include <cuda_runtime.h>
#include <cuda_bf16.h>
#include <cuda_fp16.h>
#include <math.h>
#include <stdint.h>

#define N_DRUG 11000
#define N_PRO  1000
#define NTOT   12000
#define NE     192000
#define OFF_MU 144000000L
#define OFF_LV 145536000L

// ---------------- static scratch (no allocations allowed) ----------------
__device__ __half g_M16[26L*N_PRO*128];
__device__ float g_pbias[128];
__device__ float g_XW1[NTOT*256];
__device__ float g_HW[NTOT*256];
__device__ int   g_cnt[NTOT];
__device__ int   g_rp[NTOT+1];
__device__ int   g_cur[NTOT];
__device__ int   g_ccol[NE];
__device__ float g_cval[NE];
__device__ __nv_bfloat16 g_Zhi[NTOT*128];
__device__ __nv_bfloat16 g_Zlo[NTOT*128];
// bf16 hi/lo activations
__device__ __nv_bfloat16 g_dxhi[N_DRUG*176], g_dxlo[N_DRUG*176];
__device__ __nv_bfloat16 g_d1hi[N_DRUG*128], g_d1lo[N_DRUG*128];
__device__ __nv_bfloat16 g_d2hi[N_DRUG*256], g_d2lo[N_DRUG*256];
__device__ __nv_bfloat16 g_Xhi[NTOT*128],    g_Xlo[NTOT*128];
__device__ __nv_bfloat16 g_H1hi[NTOT*256],   g_H1lo[NTOT*256];
// bf16 hi/lo transposed weights
__device__ __nv_bfloat16 g_w1thi[128*176],  g_w1tlo[128*176];
__device__ __nv_bfloat16 g_w2thi[256*128],  g_w2tlo[256*128];
__device__ __nv_bfloat16 g_w3thi[128*256],  g_w3tlo[128*256];
__device__ __nv_bfloat16 g_gc1thi[256*128], g_gc1tlo[256*128];
__device__ __nv_bfloat16 g_gc23thi[256*256],g_gc23tlo[256*256];
__device__ __nv_bfloat16 g_W2dhi[N_PRO*256],g_W2dlo[N_PRO*256];
__device__ __nv_bfloat16 g_Gtthi[26L*128*256], g_Gttlo[26L*128*256];

__device__ __forceinline__ uint32_t smem_to_u32(const void* smem_ptr) {
    uint32_t addr;
    asm("{ .reg .u64 tmp; cvta.to.shared.u64 tmp, %1; cvt.u32.u64 %0, tmp; }"
        : "=r"(addr) : "l"(smem_ptr));
    return addr;
}

// ---------------- warp-level tensor-core primitives (sm_80+ baseline PTX) ----
#define LDSM_X4(r, addr) \
    asm volatile("ldmatrix.sync.aligned.m8n8.x4.shared.b16 {%0,%1,%2,%3}, [%4];" \
        : "=r"((r)[0]), "=r"((r)[1]), "=r"((r)[2]), "=r"((r)[3]) : "r"(addr))
#define LDSM_X2(r, addr) \
    asm volatile("ldmatrix.sync.aligned.m8n8.x2.shared.b16 {%0,%1}, [%2];" \
        : "=r"((r)[0]), "=r"((r)[1]) : "r"(addr))
#define MMA_BF16(c, a, b) \
    asm volatile("mma.sync.aligned.m16n8k16.row.col.f32.bf16.bf16.f32 " \
        "{%0,%1,%2,%3}, {%4,%5,%6,%7}, {%8,%9}, {%0,%1,%2,%3};" \
        : "+f"((c)[0]), "+f"((c)[1]), "+f"((c)[2]), "+f"((c)[3]) \
        : "r"((a)[0]), "r"((a)[1]), "r"((a)[2]), "r"((a)[3]), \
          "r"((b)[0]), "r"((b)[1]))

#define SY_PITCH_B 272
#define SY_TILE_BYTES (128 * SY_PITCH_B)          // 34816
#define GM_SMEM_TOTAL (4 * SY_TILE_BYTES)         // 139264 (gemm)
#define SY_SMEM_TOTAL (6 * SY_TILE_BYTES)         // 208896 (syrk, paired j)

__device__ __forceinline__ void bf16split(float v, __nv_bfloat16& h, __nv_bfloat16& l) {
    h = __float2bfloat16(v);
    l = __float2bfloat16(v - __bfloat162float(h));
}

// ---------------- CSR build ----------------
__global__ void count_kernel(const int* __restrict__ rows) {
    int e = blockIdx.x * 256 + threadIdx.x;
    if (e < NE) atomicAdd(&g_cnt[rows[e]], 1);
}
__global__ void scan_kernel() {
    __shared__ int sums[1024];
    int tid = threadIdx.x;
    const int CH = (NTOT + 1023) / 1024;   // 12
    int base = tid * CH;
    int s = 0;
    for (int i = 0; i < CH; i++) { int idx = base + i; if (idx < NTOT) s += g_cnt[idx]; }
    sums[tid] = s;
    __syncthreads();
    for (int off = 1; off < 1024; off <<= 1) {
        int v = 0;
        if (tid >= off) v = sums[tid - off];
        __syncthreads();
        sums[tid] += v;
        __syncthreads();
    }
    int prefix = (tid == 0) ? 0 : sums[tid - 1];
    for (int i = 0; i < CH; i++) {
        int idx = base + i;
        if (idx < NTOT) { g_rp[idx] = prefix; g_cur[idx] = prefix; prefix += g_cnt[idx]; }
    }
    if (tid == 1023) g_rp[NTOT] = NE;
}
__global__ void scatter_kernel(const int* __restrict__ rows, const int* __restrict__ cols,
                               const float* __restrict__ vals) {
    int e = blockIdx.x * 256 + threadIdx.x;
    if (e < NE) {
        int r = rows[e];
        int pos = atomicAdd(&g_cur[r], 1);
        g_ccol[pos] = cols[e];
        g_cval[pos] = vals[e];
    }
}

// ---------------- merged prep kernel (all weight splits/repacks) -------------
// block ranges:
#define PS0 7563                 // dxsplit       (11000*176/256)
#define PS1 (PS0 + 88)           // w1t
#define PS2 (PS1 + 128)          // w2t
#define PS3 (PS2 + 128)          // w3t
#define PS4 (PS3 + 128)          // gc1t
#define PS5 (PS4 + 256)          // gc23t
#define PS6 (PS5 + 1000)         // repack conv_w
#define PS7 (PS6 + 832)          // G per (t,o): 26*32 blocks
#define PS8 (PS7 + 1)            // pbias
__device__ __forceinline__ void prep_tsplit(int lidx, const float* __restrict__ W,
                                            int K, int N, int ldt,
                                            __nv_bfloat16* Thi, __nv_bfloat16* Tlo) {
    if (lidx < N * ldt) {
        int n = lidx / ldt, k = lidx - n * ldt;
        float v = (k < K) ? W[(long)k * N + n] : 0.f;
        bf16split(v, Thi[lidx], Tlo[lidx]);
    }
}
__global__ void prep_kernel(const float* __restrict__ dx,
                            const float* __restrict__ w1, const float* __restrict__ w2,
                            const float* __restrict__ w3, const float* __restrict__ gc1,
                            const float* __restrict__ gc2, const float* __restrict__ gc3,
                            const float* __restrict__ conv_w,
                            const float* __restrict__ emb, const float* __restrict__ fc_w,
                            const float* __restrict__ fc_b, const float* __restrict__ conv_b) {
    int b = blockIdx.x, tid = threadIdx.x;
    if (b < PS0) {
        int idx = b * 256 + tid;
        if (idx < N_DRUG * 176) {
            int row = idx / 176, col = idx - row * 176;
            float v = (col < 167) ? dx[(long)row * 167 + col] : 0.f;
            bf16split(v, g_dxhi[idx], g_dxlo[idx]);
        }
    } else if (b < PS1) {
        prep_tsplit((b - PS0) * 256 + tid, w1, 167, 128, 176, g_w1thi, g_w1tlo);
    } else if (b < PS2) {
        prep_tsplit((b - PS1) * 256 + tid, w2, 128, 256, 128, g_w2thi, g_w2tlo);
    } else if (b < PS3) {
        prep_tsplit((b - PS2) * 256 + tid, w3, 256, 128, 256, g_w3thi, g_w3tlo);
    } else if (b < PS4) {
        prep_tsplit((b - PS3) * 256 + tid, gc1, 128, 256, 128, g_gc1thi, g_gc1tlo);
    } else if (b < PS5) {
        int idx = (b - PS4) * 256 + tid;   // n*256 + k
        int n = idx >> 8, k = idx & 255;
        float v = (n < 128) ? gc2[k * 128 + n] : gc3[k * 128 + n - 128];
        bf16split(v, g_gc23thi[idx], g_gc23tlo[idx]);
    } else if (b < PS6) {
        int idx = (b - PS5) * 256 + tid;
        if (idx < N_PRO * 256) {
            int i = idx >> 8, ok = idx & 255;
            int o = ok >> 3, k = ok & 7;
            float v = conv_w[((long)o * N_PRO + i) * 8 + k];
            bf16split(v, g_W2dhi[idx], g_W2dlo[idx]);
        }
    } else if (b < PS7) {
        // G per (t,o): each fc_w row applied to 8 kk offsets (4 per thread-half).
        // Gtt[t][f][o*8+kk] = sum_h emb[t, h+kk] * fc_w[(o*121+h)*128 + f]
        __shared__ float e[128];
        int idx = b - PS6;
        int t = idx >> 5, o = idx & 31;
        int half = tid >> 7, f = tid & 127;
        if (tid < 128) e[tid] = emb[t * 128 + tid];
        __syncthreads();
        float acc[4] = {0.f, 0.f, 0.f, 0.f};
        const float* wrow = fc_w + (long)o * 121 * 128 + f;
        int kbase = half * 4;
        for (int h = 0; h < 121; h++) {
            float w = wrow[h * 128];
#pragma unroll
            for (int kk = 0; kk < 4; kk++)
                acc[kk] += e[h + kbase + kk] * w;
        }
        long dbase = ((long)t * 128 + f) * 256 + o * 8 + kbase;
#pragma unroll
        for (int kk = 0; kk < 4; kk++)
            bf16split(acc[kk], g_Gtthi[dbase + kk], g_Gttlo[dbase + kk]);
    } else {
        int f = tid;
        if (f < 128) {
            float acc = fc_b[f];
            for (int o = 0; o < 32; o++) {
                float cb = conv_b[o];
                for (int h = 0; h < 121; h++) acc += cb * fc_w[(o * 121 + h) * 128 + f];
            }
            g_pbias[f] = acc;
        }
    }
}

__global__ void protein_gather_kernel(const int* __restrict__ pro_x) {
    int p = blockIdx.x, f = threadIdx.x;   // 1000 blocks x 128
    __shared__ int tok[128];
    float acc = g_pbias[f];
    for (int c = 0; c < 1000; c += 128) {
        int n = min(128, 1000 - c);
        if (f < n) tok[f] = pro_x[p * 1000 + c + f];
        __syncthreads();
#pragma unroll 8
        for (int ii = 0; ii < n; ii++) {
            int t = tok[ii];
            acc += __half2float(g_M16[((long)t * N_PRO + c + ii) * 128 + f]);
        }
        __syncthreads();
    }
    long dst = (long)(N_DRUG + p) * 128 + f;
    bf16split(acc, g_Xhi[dst], g_Xlo[dst]);
}

// ---------------- SpMM (CSR gather), F=256 ----------------------------------
__global__ void spmm256_kernel(const float* __restrict__ Xin,
                               float* __restrict__ out1, float* __restrict__ out2,
                               __nv_bfloat16* __restrict__ bh, __nv_bfloat16* __restrict__ bl,
                               int relu, int split128) {
    int r = blockIdx.x;
    int f = threadIdx.x;   // 256
    int e0 = g_rp[r], e1 = g_rp[r + 1];
    float acc = 0.f;
    for (int e = e0; e < e1; e++) {
        int c = g_ccol[e];
        float v = g_cval[e];
        acc += v * Xin[(long)c * 256 + f];
    }
    if (relu) acc = fmaxf(acc, 0.f);
    if (split128) {
        if (f < 128) {
            out1[(long)r * 128 + f] = acc;
            bf16split(acc, bh[(long)r * 128 + f], bl[(long)r * 128 + f]);
        } else {
            out2[(long)r * 128 + f - 128] = acc;
        }
    } else {
        bf16split(acc, bh[(long)r * 256 + f], bl[(long)r * 256 + f]);
    }
}

// ---------------- tensor-core GEMM: C[M,N] = A[M,K] @ Bt[N,K]^T --------------
__global__ __launch_bounds__(256, 1) void gemm_mma_kernel(
    const __nv_bfloat16* __restrict__ Ahi, const __nv_bfloat16* __restrict__ Alo, int lda,
    const __nv_bfloat16* __restrict__ Bhi, const __nv_bfloat16* __restrict__ Blo, int ldb,
    const float* __restrict__ bias,
    float* __restrict__ Cf, __half* __restrict__ C16,
    __nv_bfloat16* __restrict__ Chi, __nv_bfloat16* __restrict__ Clo,
    int ldc, int M, int N, int K, int relu, long sB, long sC)
{
    Bhi += (long)blockIdx.z * sB;
    Blo += (long)blockIdx.z * sB;
    long coff = (long)blockIdx.z * sC;
    extern __shared__ char smem[];
    uint32_t sb = smem_to_u32(smem);

    int tid = threadIdx.x, lane = tid & 31, wid = tid >> 5;
    int m0 = blockIdx.y * 128, n0 = blockIdx.x * 128;

    int mw = (wid & 1) << 6;
    int nw = (wid >> 1) << 5;
    float acc[4][4][4];
#pragma unroll
    for (int a = 0; a < 4; a++)
#pragma unroll
        for (int b = 0; b < 4; b++)
#pragma unroll
            for (int c = 0; c < 4; c++) acc[a][b][c] = 0.f;

    int arow = mw + (lane & 15);
    uint32_t acol = ((uint32_t)(lane >> 4)) * 16u;
    int brow = nw + (lane & 7);
    uint32_t bcol = ((uint32_t)((lane >> 3) & 1)) * 16u;

    int r = tid >> 1, half = tid & 1;

    for (int k0 = 0; k0 < K; k0 += 128) {
        {
            const __nv_bfloat16* srcs[4] = {Ahi, Alo, Bhi, Blo};
            int lds[4]   = {lda, lda, ldb, ldb};
            int base[4]  = {m0, m0, n0, n0};
            int limit[4] = {M, M, N, N};
#pragma unroll
            for (int tI = 0; tI < 4; tI++) {
                long gr = (long)base[tI] + r;
                bool rv = gr < limit[tI];
                const __nv_bfloat16* sp = srcs[tI] + gr * (long)lds[tI] + k0 + half * 64;
                uint4* d = (uint4*)(smem + tI * SY_TILE_BYTES + r * SY_PITCH_B + half * 128);
#pragma unroll
                for (int c = 0; c < 8; c++) {
                    int col0 = half * 64 + c * 8;
                    uint4 v = make_uint4(0, 0, 0, 0);
                    if (rv && (k0 + col0 + 8) <= K) v = *(const uint4*)(sp + c * 8);
                    d[c] = v;
                }
            }
        }
        __syncthreads();

        int ksteps = (K - k0) >= 128 ? 8 : ((K - k0 + 15) >> 4);
        uint32_t offA_hi = 0, offA_lo = SY_TILE_BYTES;
        uint32_t offB_hi = 2u * SY_TILE_BYTES, offB_lo = 3u * SY_TILE_BYTES;
        for (int ks = 0; ks < ksteps; ks++) {
            uint32_t kb = (uint32_t)ks * 32u;
            uint32_t bh[4][2], bl[4][2];
#pragma unroll
            for (int nf = 0; nf < 4; nf++) {
                uint32_t ro = (uint32_t)(brow + nf * 8) * SY_PITCH_B + kb + bcol;
                LDSM_X2(bh[nf], sb + offB_hi + ro);
                LDSM_X2(bl[nf], sb + offB_lo + ro);
            }
#pragma unroll
            for (int mf = 0; mf < 4; mf++) {
                uint32_t ro = (uint32_t)(arow + mf * 16) * SY_PITCH_B + kb + acol;
                uint32_t ah[4], al[4];
                LDSM_X4(ah, sb + offA_hi + ro);
                LDSM_X4(al, sb + offA_lo + ro);
#pragma unroll
                for (int nf = 0; nf < 4; nf++) {
                    MMA_BF16(acc[mf][nf], ah, bh[nf]);
                    MMA_BF16(acc[mf][nf], ah, bl[nf]);
                    MMA_BF16(acc[mf][nf], al, bh[nf]);
                }
            }
        }
        __syncthreads();
    }

    // epilogue
    int mrow = lane >> 2, ncol = (lane & 3) * 2;
#pragma unroll
    for (int mf = 0; mf < 4; mf++) {
#pragma unroll
        for (int nf = 0; nf < 4; nf++) {
            long gm = m0 + mw + mf * 16 + mrow;
            int gn = n0 + nw + nf * 8 + ncol;
            float v0 = acc[mf][nf][0], v1 = acc[mf][nf][1];
            float v2 = acc[mf][nf][2], v3 = acc[mf][nf][3];
            if (bias) {
                float b0 = bias[gn], b1 = bias[gn + 1];
                v0 += b0; v1 += b1; v2 += b0; v3 += b1;
            }
            if (relu) {
                v0 = fmaxf(v0, 0.f); v1 = fmaxf(v1, 0.f);
                v2 = fmaxf(v2, 0.f); v3 = fmaxf(v3, 0.f);
            }
            if (gm < M) {
                long o = coff + gm * (long)ldc + gn;
                if (Cf) *(float2*)&Cf[o] = make_float2(v0, v1);
                if (C16) *(__half2*)&C16[o] = __floats2half2_rn(v0, v1);
                if (Chi) {
                    __nv_bfloat162 h, l;
                    bf16split(v0, h.x, l.x); bf16split(v1, h.y, l.y);
                    *(__nv_bfloat162*)&Chi[o] = h;
                    *(__nv_bfloat162*)&Clo[o] = l;
                }
            }
            if (gm + 8 < M) {
                long o = coff + (gm + 8) * (long)ldc + gn;
                if (Cf) *(float2*)&Cf[o] = make_float2(v2, v3);
                if (C16) *(__half2*)&C16[o] = __floats2half2_rn(v2, v3);
                if (Chi) {
                    __nv_bfloat162 h, l;
                    bf16split(v2, h.x, l.x); bf16split(v3, h.y, l.y);
                    *(__nv_bfloat162*)&Chi[o] = h;
                    *(__nv_bfloat162*)&Clo[o] = l;
                }
            }
        }
    }
}

// ---------------- SYRK via mma.sync bf16 hi/lo: C = Z Z^T --------------------
// Paired-j: one CTA handles tiles (i,j0) and (i,j0+1). Smem: 6 tiles.
__device__ __forceinline__ void ld_tile(char* smem, int off,
                                        const __nv_bfloat16* __restrict__ src,
                                        long row0, int r, int half) {
    long gr = row0 + r;
    uint4 v[8];
    if (gr < NTOT) {
        const uint4* s = reinterpret_cast<const uint4*>(src + gr * 128 + half * 64);
#pragma unroll
        for (int c = 0; c < 8; c++) v[c] = s[c];
    } else {
#pragma unroll
        for (int c = 0; c < 8; c++) v[c] = make_uint4(0, 0, 0, 0);
    }
    uint4* d = reinterpret_cast<uint4*>(smem + off + r * SY_PITCH_B + half * 128);
#pragma unroll
    for (int c = 0; c < 8; c++) d[c] = v[c];
}

__device__ __forceinline__ void syrk_tile(uint32_t sb, uint32_t offBh, uint32_t offBl,
                                          long i0, long j0, bool mirror,
                                          float* __restrict__ C, int lane, int wid) {
    int mw = (wid & 1) << 6;
    int nw = (wid >> 1) << 5;
    float acc[4][4][4];
#pragma unroll
    for (int a = 0; a < 4; a++)
#pragma unroll
        for (int b = 0; b < 4; b++)
#pragma unroll
            for (int c = 0; c < 4; c++) acc[a][b][c] = 0.f;

    int arow = mw + (lane & 15);
    uint32_t acol = ((uint32_t)(lane >> 4)) * 16u;
    int brow = nw + (lane & 7);
    uint32_t bcol = ((uint32_t)((lane >> 3) & 1)) * 16u;

#pragma unroll
    for (int ks = 0; ks < 8; ks++) {
        uint32_t kb = (uint32_t)ks * 32u;
        uint32_t bh[4][2], bl[4][2];
#pragma unroll
        for (int nf = 0; nf < 4; nf++) {
            uint32_t ro = (uint32_t)(brow + nf * 8) * SY_PITCH_B + kb + bcol;
            LDSM_X2(bh[nf], sb + offBh + ro);
            LDSM_X2(bl[nf], sb + offBl + ro);
        }
#pragma unroll
        for (int mf = 0; mf < 4; mf++) {
            uint32_t ro = (uint32_t)(arow + mf * 16) * SY_PITCH_B + kb + acol;
            uint32_t ah[4], al[4];
            LDSM_X4(ah, sb + 0 + ro);
            LDSM_X4(al, sb + SY_TILE_BYTES + ro);
#pragma unroll
            for (int nf = 0; nf < 4; nf++) {
                MMA_BF16(acc[mf][nf], ah, bh[nf]);
                MMA_BF16(acc[mf][nf], ah, bl[nf]);
                MMA_BF16(acc[mf][nf], al, bh[nf]);
            }
        }
    }

    int mrow = lane >> 2, ncol = (lane & 3) * 2;
#pragma unroll
    for (int mf = 0; mf < 4; mf++) {
#pragma unroll
        for (int nf = 0; nf < 4; nf++) {
            long gm = i0 + mw + mf * 16 + mrow;
            long gn = j0 + nw + nf * 8 + ncol;
            float v0 = acc[mf][nf][0], v1 = acc[mf][nf][1];
            float v2 = acc[mf][nf][2], v3 = acc[mf][nf][3];
            if (gn < NTOT) {
                if (gm < NTOT)
                    *(float2*)&C[gm * (long)NTOT + gn] = make_float2(v0, v1);
                if (gm + 8 < NTOT)
                    *(float2*)&C[(gm + 8) * (long)NTOT + gn] = make_float2(v2, v3);
            }
            if (mirror) {
                if (gn < NTOT) {
                    if (gm < NTOT)      C[gn * (long)NTOT + gm] = v0;
                    if (gm + 8 < NTOT)  C[gn * (long)NTOT + gm + 8] = v2;
                }
                if (gn + 1 < NTOT) {
                    if (gm < NTOT)      C[(gn + 1) * (long)NTOT + gm] = v1;
                    if (gm + 8 < NTOT)  C[(gn + 1) * (long)NTOT + gm + 8] = v3;
                }
            }
        }
    }
}

__global__ __launch_bounds__(256, 1) void syrk_mma_kernel(float* __restrict__ C) {
    extern __shared__ char smem[];
    int rem = blockIdx.x;
    int i = 0;
    while (true) {
        int np = (95 - i) >> 1;
        if (rem < np) break;
        rem -= np;
        i++;
    }
    int j0 = i + 2 * rem;
    int j1 = j0 + 1;
    bool has2 = (j1 <= 93);
    long i0 = (long)i * 128, jj0 = (long)j0 * 128, jj1 = (long)j1 * 128;

    int tid = threadIdx.x, lane = tid & 31, wid = tid >> 5;

    {
        int r = tid >> 1, half = tid & 1;
        ld_tile(smem, 0,                 g_Zhi, i0, r, half);
        ld_tile(smem, SY_TILE_BYTES,     g_Zlo, i0, r, half);
        ld_tile(smem, 2 * SY_TILE_BYTES, g_Zhi, jj0, r, half);
        ld_tile(smem, 3 * SY_TILE_BYTES, g_Zlo, jj0, r, half);
        if (has2) {
            ld_tile(smem, 4 * SY_TILE_BYTES, g_Zhi, jj1, r, half);
            ld_tile(smem, 5 * SY_TILE_BYTES, g_Zlo, jj1, r, half);
        }
    }
    __syncthreads();

    uint32_t sb = smem_to_u32(smem);
    syrk_tile(sb, 2u * SY_TILE_BYTES, 3u * SY_TILE_BYTES, i0, jj0, j0 != i, C, lane, wid);
    if (has2)
        syrk_tile(sb, 4u * SY_TILE_BYTES, 5u * SY_TILE_BYTES, i0, jj1, true, C, lane, wid);
}

// ---------------- host ----------------
extern "C" void kernel_launch(void* const* d_in, const int* in_sizes, int n_in,
                              void* d_out, int out_size) {
    const float* drug_x = (const float*)d_in[0];
    const int*   pro_x  = (const int*)d_in[1];
    const int*   arows  = (const int*)d_in[2];
    const int*   acols  = (const int*)d_in[3];
    const float* avals  = (const float*)d_in[4];
    const float* w1     = (const float*)d_in[5];
    const float* b1     = (const float*)d_in[6];
    const float* w2     = (const float*)d_in[7];
    const float* b2     = (const float*)d_in[8];
    const float* w3     = (const float*)d_in[9];
    const float* b3     = (const float*)d_in[10];
    const float* emb_xt = (const float*)d_in[11];
    const float* conv_w = (const float*)d_in[12];
    const float* conv_b = (const float*)d_in[13];
    const float* fc_w   = (const float*)d_in[14];
    const float* fc_b   = (const float*)d_in[15];
    const float* gc1_w  = (const float*)d_in[16];
    const float* gc2_w  = (const float*)d_in[17];
    const float* gc3_w  = (const float*)d_in[18];
    float* out = (float*)d_out;

    float *pXW1, *pHW;
    __half* pM16;
    int *pcnt;
    cudaGetSymbolAddress((void**)&pM16, g_M16);
    cudaGetSymbolAddress((void**)&pXW1, g_XW1);
    cudaGetSymbolAddress((void**)&pHW,  g_HW);
    cudaGetSymbolAddress((void**)&pcnt, g_cnt);
    __nv_bfloat16 *pdxh,*pdxl,*pd1h,*pd1l,*pd2h,*pd2l,*pXh,*pXl,*pH1h,*pH1l;
    __nv_bfloat16 *pw1h,*pw1l,*pw2h,*pw2l,*pw3h,*pw3l,*pg1h,*pg1l,*pg23h,*pg23l;
    __nv_bfloat16 *pW2h,*pW2l,*pGth,*pGtl,*pZh,*pZl;
    cudaGetSymbolAddress((void**)&pdxh, g_dxhi);  cudaGetSymbolAddress((void**)&pdxl, g_dxlo);
    cudaGetSymbolAddress((void**)&pd1h, g_d1hi);  cudaGetSymbolAddress((void**)&pd1l, g_d1lo);
    cudaGetSymbolAddress((void**)&pd2h, g_d2hi);  cudaGetSymbolAddress((void**)&pd2l, g_d2lo);
    cudaGetSymbolAddress((void**)&pXh,  g_Xhi);   cudaGetSymbolAddress((void**)&pXl,  g_Xlo);
    cudaGetSymbolAddress((void**)&pH1h, g_H1hi);  cudaGetSymbolAddress((void**)&pH1l, g_H1lo);
    cudaGetSymbolAddress((void**)&pw1h, g_w1thi); cudaGetSymbolAddress((void**)&pw1l, g_w1tlo);
    cudaGetSymbolAddress((void**)&pw2h, g_w2thi); cudaGetSymbolAddress((void**)&pw2l, g_w2tlo);
    cudaGetSymbolAddress((void**)&pw3h, g_w3thi); cudaGetSymbolAddress((void**)&pw3l, g_w3tlo);
    cudaGetSymbolAddress((void**)&pg1h, g_gc1thi);cudaGetSymbolAddress((void**)&pg1l, g_gc1tlo);
    cudaGetSymbolAddress((void**)&pg23h,g_gc23thi);cudaGetSymbolAddress((void**)&pg23l,g_gc23tlo);
    cudaGetSymbolAddress((void**)&pW2h, g_W2dhi); cudaGetSymbolAddress((void**)&pW2l, g_W2dlo);
    cudaGetSymbolAddress((void**)&pGth, g_Gtthi); cudaGetSymbolAddress((void**)&pGtl, g_Gttlo);
    cudaGetSymbolAddress((void**)&pZh,  g_Zhi);   cudaGetSymbolAddress((void**)&pZl,  g_Zlo);

    static int smem_set = 0;
    if (!smem_set) {
        cudaFuncSetAttribute(syrk_mma_kernel, cudaFuncAttributeMaxDynamicSharedMemorySize,
                             SY_SMEM_TOTAL);
        cudaFuncSetAttribute(gemm_mma_kernel, cudaFuncAttributeMaxDynamicSharedMemorySize,
                             GM_SMEM_TOTAL);
        smem_set = 1;
    }

    // CSR build
    cudaMemsetAsync(pcnt, 0, NTOT * sizeof(int));
    count_kernel<<<750, 256>>>(arows);
    scan_kernel<<<1, 1024>>>();
    scatter_kernel<<<750, 256>>>(arows, acols, avals);

    // merged prep (all splits/repacks/G/pbias)
    prep_kernel<<<PS8, 256>>>(drug_x, w1, w2, w3, gc1_w, gc2_w, gc3_w,
                              conv_w, emb_xt, fc_w, fc_b, conv_b);

    // drug MLP (tensor cores)
    gemm_mma_kernel<<<dim3(1, 86, 1), 256, GM_SMEM_TOTAL>>>(
        pdxh, pdxl, 176, pw1h, pw1l, 176, b1,
        nullptr, nullptr, pd1h, pd1l, 128, N_DRUG, 128, 176, 1, 0, 0);
    gemm_mma_kernel<<<dim3(2, 86, 1), 256, GM_SMEM_TOTAL>>>(
        pd1h, pd1l, 128, pw2h, pw2l, 128, b2,
        nullptr, nullptr, pd2h, pd2l, 256, N_DRUG, 256, 128, 1, 0, 0);
    gemm_mma_kernel<<<dim3(1, 86, 1), 256, GM_SMEM_TOTAL>>>(
        pd2h, pd2l, 256, pw3h, pw3l, 256, b3,
        nullptr, nullptr, pXh, pXl, 128, N_DRUG, 128, 256, 1, 0, 0);

    // protein: M[t] = W2d @ Gt[t]  (batched, tensor cores, fp16 output)
    gemm_mma_kernel<<<dim3(1, 8, 26), 256, GM_SMEM_TOTAL>>>(
        pW2h, pW2l, 256, pGth, pGtl, 256, nullptr,
        nullptr, pM16, nullptr, nullptr, 128, N_PRO, 128, 256, 0,
        128L * 256, (long)N_PRO * 128);
    protein_gather_kernel<<<1000, 128>>>(pro_x);

    // GCN encoder
    gemm_mma_kernel<<<dim3(2, 94, 1), 256, GM_SMEM_TOTAL>>>(
        pXh, pXl, 128, pg1h, pg1l, 128, nullptr,
        pXW1, nullptr, nullptr, nullptr, 256, NTOT, 256, 128, 0, 0, 0);
    spmm256_kernel<<<NTOT, 256>>>(pXW1, nullptr, nullptr, pH1h, pH1l, 1, 0);
    gemm_mma_kernel<<<dim3(2, 94, 1), 256, GM_SMEM_TOTAL>>>(
        pH1h, pH1l, 256, pg23h, pg23l, 256, nullptr,
        pHW, nullptr, nullptr, nullptr, 256, NTOT, 256, 256, 0, 0, 0);
    spmm256_kernel<<<NTOT, 256>>>(pHW, out + OFF_MU, out + OFF_LV, pZh, pZl, 0, 1);

    // decoder: adj_rec = Z Z^T (paired-j tiles)
    syrk_mma_kernel<<<2256, 256, SY_SMEM_TOTAL>>>(out);
}

// round 11
// speedup vs baseline: 1.0034x; 1.0034x over previous
#include <cuda_runtime.h>
#include <cuda_bf16.h>
#include <cuda_fp16.h>
#include <math.h>
#include <stdint.h>

#define N_DRUG 11000
#define N_PRO  1000
#define NTOT   12000
#define NE     192000
#define OFF_MU 144000000L
#define OFF_LV 145536000L

// ---------------- static scratch (no allocations allowed) ----------------
__device__ __half g_M16[26L*N_PRO*128];
__device__ float g_pbias[128];
__device__ float g_XW1[NTOT*256];
__device__ float g_HW[NTOT*256];
__device__ int   g_cnt[NTOT];
__device__ int   g_rp[NTOT+1];
__device__ int   g_cur[NTOT];
__device__ int   g_ccol[NE];
__device__ float g_cval[NE];
__device__ __nv_bfloat16 g_Zhi[NTOT*128];
__device__ __nv_bfloat16 g_Zlo[NTOT*128];
// bf16 hi/lo activations
__device__ __nv_bfloat16 g_dxhi[N_DRUG*176], g_dxlo[N_DRUG*176];
__device__ __nv_bfloat16 g_d1hi[N_DRUG*128], g_d1lo[N_DRUG*128];
__device__ __nv_bfloat16 g_d2hi[N_DRUG*256], g_d2lo[N_DRUG*256];
__device__ __nv_bfloat16 g_Xhi[NTOT*128],    g_Xlo[NTOT*128];
__device__ __nv_bfloat16 g_H1hi[NTOT*256],   g_H1lo[NTOT*256];
// bf16 hi/lo transposed weights
__device__ __nv_bfloat16 g_w1thi[128*176],  g_w1tlo[128*176];
__device__ __nv_bfloat16 g_w2thi[256*128],  g_w2tlo[256*128];
__device__ __nv_bfloat16 g_w3thi[128*256],  g_w3tlo[128*256];
__device__ __nv_bfloat16 g_gc1thi[256*128], g_gc1tlo[256*128];
__device__ __nv_bfloat16 g_gc23thi[256*256],g_gc23tlo[256*256];
__device__ __nv_bfloat16 g_W2dhi[N_PRO*256],g_W2dlo[N_PRO*256];
__device__ __nv_bfloat16 g_Gtthi[26L*128*256], g_Gttlo[26L*128*256];

__device__ __forceinline__ uint32_t smem_to_u32(const void* smem_ptr) {
    uint32_t addr;
    asm("{ .reg .u64 tmp; cvta.to.shared.u64 tmp, %1; cvt.u32.u64 %0, tmp; }"
        : "=r"(addr) : "l"(smem_ptr));
    return addr;
}

// ---------------- warp-level tensor-core primitives (sm_80+ baseline PTX) ----
#define LDSM_X4(r, addr) \
    asm volatile("ldmatrix.sync.aligned.m8n8.x4.shared.b16 {%0,%1,%2,%3}, [%4];" \
        : "=r"((r)[0]), "=r"((r)[1]), "=r"((r)[2]), "=r"((r)[3]) : "r"(addr))
#define LDSM_X2(r, addr) \
    asm volatile("ldmatrix.sync.aligned.m8n8.x2.shared.b16 {%0,%1}, [%2];" \
        : "=r"((r)[0]), "=r"((r)[1]) : "r"(addr))
#define MMA_BF16(c, a, b) \
    asm volatile("mma.sync.aligned.m16n8k16.row.col.f32.bf16.bf16.f32 " \
        "{%0,%1,%2,%3}, {%4,%5,%6,%7}, {%8,%9}, {%0,%1,%2,%3};" \
        : "+f"((c)[0]), "+f"((c)[1]), "+f"((c)[2]), "+f"((c)[3]) \
        : "r"((a)[0]), "r"((a)[1]), "r"((a)[2]), "r"((a)[3]), \
          "r"((b)[0]), "r"((b)[1]))

#define SY_PITCH_B 272
#define SY_TILE_BYTES (128 * SY_PITCH_B)          // 34816
#define GM_SMEM_TOTAL (4 * SY_TILE_BYTES)         // 139264 (gemm)
#define SY_SMEM_TOTAL (6 * SY_TILE_BYTES)         // 208896 (syrk, paired j)

__device__ __forceinline__ void bf16split(float v, __nv_bfloat16& h, __nv_bfloat16& l) {
    h = __float2bfloat16(v);
    l = __float2bfloat16(v - __bfloat162float(h));
}

// ---------------- CSR build ----------------
__global__ void count_kernel(const int* __restrict__ rows) {
    int e = blockIdx.x * 256 + threadIdx.x;
    if (e < NE) atomicAdd(&g_cnt[rows[e]], 1);
}
__global__ void scan_kernel() {
    __shared__ int sums[1024];
    int tid = threadIdx.x;
    const int CH = (NTOT + 1023) / 1024;   // 12
    int base = tid * CH;
    int s = 0;
    for (int i = 0; i < CH; i++) { int idx = base + i; if (idx < NTOT) s += g_cnt[idx]; }
    sums[tid] = s;
    __syncthreads();
    for (int off = 1; off < 1024; off <<= 1) {
        int v = 0;
        if (tid >= off) v = sums[tid - off];
        __syncthreads();
        sums[tid] += v;
        __syncthreads();
    }
    int prefix = (tid == 0) ? 0 : sums[tid - 1];
    for (int i = 0; i < CH; i++) {
        int idx = base + i;
        if (idx < NTOT) { g_rp[idx] = prefix; g_cur[idx] = prefix; prefix += g_cnt[idx]; }
    }
    if (tid == 1023) g_rp[NTOT] = NE;
}
__global__ void scatter_kernel(const int* __restrict__ rows, const int* __restrict__ cols,
                               const float* __restrict__ vals) {
    int e = blockIdx.x * 256 + threadIdx.x;
    if (e < NE) {
        int r = rows[e];
        int pos = atomicAdd(&g_cur[r], 1);
        g_ccol[pos] = cols[e];
        g_cval[pos] = vals[e];
    }
}

// ---------------- merged prep kernel (all weight splits/repacks) -------------
// block ranges:
#define PS0 7563                 // dxsplit       (11000*176/256)
#define PS1 (PS0 + 88)           // w1t
#define PS2 (PS1 + 128)          // w2t
#define PS3 (PS2 + 128)          // w3t
#define PS4 (PS3 + 128)          // gc1t
#define PS5 (PS4 + 256)          // gc23t
#define PS6 (PS5 + 1000)         // repack conv_w
#define PS7 (PS6 + 832)          // G per (t,o): 26*32 blocks
#define PS8 (PS7 + 1)            // pbias
__device__ __forceinline__ void prep_tsplit(int lidx, const float* __restrict__ W,
                                            int K, int N, int ldt,
                                            __nv_bfloat16* Thi, __nv_bfloat16* Tlo) {
    if (lidx < N * ldt) {
        int n = lidx / ldt, k = lidx - n * ldt;
        float v = (k < K) ? W[(long)k * N + n] : 0.f;
        bf16split(v, Thi[lidx], Tlo[lidx]);
    }
}
__global__ void prep_kernel(const float* __restrict__ dx,
                            const float* __restrict__ w1, const float* __restrict__ w2,
                            const float* __restrict__ w3, const float* __restrict__ gc1,
                            const float* __restrict__ gc2, const float* __restrict__ gc3,
                            const float* __restrict__ conv_w,
                            const float* __restrict__ emb, const float* __restrict__ fc_w,
                            const float* __restrict__ fc_b, const float* __restrict__ conv_b) {
    int b = blockIdx.x, tid = threadIdx.x;
    if (b < PS0) {
        int idx = b * 256 + tid;
        if (idx < N_DRUG * 176) {
            int row = idx / 176, col = idx - row * 176;
            float v = (col < 167) ? dx[(long)row * 167 + col] : 0.f;
            bf16split(v, g_dxhi[idx], g_dxlo[idx]);
        }
    } else if (b < PS1) {
        prep_tsplit((b - PS0) * 256 + tid, w1, 167, 128, 176, g_w1thi, g_w1tlo);
    } else if (b < PS2) {
        prep_tsplit((b - PS1) * 256 + tid, w2, 128, 256, 128, g_w2thi, g_w2tlo);
    } else if (b < PS3) {
        prep_tsplit((b - PS2) * 256 + tid, w3, 256, 128, 256, g_w3thi, g_w3tlo);
    } else if (b < PS4) {
        prep_tsplit((b - PS3) * 256 + tid, gc1, 128, 256, 128, g_gc1thi, g_gc1tlo);
    } else if (b < PS5) {
        int idx = (b - PS4) * 256 + tid;   // n*256 + k
        int n = idx >> 8, k = idx & 255;
        float v = (n < 128) ? gc2[k * 128 + n] : gc3[k * 128 + n - 128];
        bf16split(v, g_gc23thi[idx], g_gc23tlo[idx]);
    } else if (b < PS6) {
        int idx = (b - PS5) * 256 + tid;
        if (idx < N_PRO * 256) {
            int i = idx >> 8, ok = idx & 255;
            int o = ok >> 3, k = ok & 7;
            float v = conv_w[((long)o * N_PRO + i) * 8 + k];
            bf16split(v, g_W2dhi[idx], g_W2dlo[idx]);
        }
    } else if (b < PS7) {
        // G per (t,o): each fc_w row applied to 8 kk offsets (4 per thread-half).
        // Gtt[t][f][o*8+kk] = sum_h emb[t, h+kk] * fc_w[(o*121+h)*128 + f]
        __shared__ float e[128];
        int idx = b - PS6;
        int t = idx >> 5, o = idx & 31;
        int half = tid >> 7, f = tid & 127;
        if (tid < 128) e[tid] = emb[t * 128 + tid];
        __syncthreads();
        float acc[4] = {0.f, 0.f, 0.f, 0.f};
        const float* wrow = fc_w + (long)o * 121 * 128 + f;
        int kbase = half * 4;
        for (int h = 0; h < 121; h++) {
            float w = wrow[h * 128];
#pragma unroll
            for (int kk = 0; kk < 4; kk++)
                acc[kk] += e[h + kbase + kk] * w;
        }
        long dbase = ((long)t * 128 + f) * 256 + o * 8 + kbase;
#pragma unroll
        for (int kk = 0; kk < 4; kk++)
            bf16split(acc[kk], g_Gtthi[dbase + kk], g_Gttlo[dbase + kk]);
    } else {
        int f = tid;
        if (f < 128) {
            float acc = fc_b[f];
            for (int o = 0; o < 32; o++) {
                float cb = conv_b[o];
                for (int h = 0; h < 121; h++) acc += cb * fc_w[(o * 121 + h) * 128 + f];
            }
            g_pbias[f] = acc;
        }
    }
}

__global__ void protein_gather_kernel(const int* __restrict__ pro_x) {
    int p = blockIdx.x, f = threadIdx.x;   // 1000 blocks x 128
    __shared__ int tok[128];
    float acc = g_pbias[f];
    for (int c = 0; c < 1000; c += 128) {
        int n = min(128, 1000 - c);
        if (f < n) tok[f] = pro_x[p * 1000 + c + f];
        __syncthreads();
#pragma unroll 8
        for (int ii = 0; ii < n; ii++) {
            int t = tok[ii];
            acc += __half2float(g_M16[((long)t * N_PRO + c + ii) * 128 + f]);
        }
        __syncthreads();
    }
    long dst = (long)(N_DRUG + p) * 128 + f;
    bf16split(acc, g_Xhi[dst], g_Xlo[dst]);
}

// ---------------- SpMM (CSR gather), F=256 ----------------------------------
__global__ void spmm256_kernel(const float* __restrict__ Xin,
                               float* __restrict__ out1, float* __restrict__ out2,
                               __nv_bfloat16* __restrict__ bh, __nv_bfloat16* __restrict__ bl,
                               int relu, int split128) {
    int r = blockIdx.x;
    int f = threadIdx.x;   // 256
    int e0 = g_rp[r], e1 = g_rp[r + 1];
    float acc = 0.f;
    for (int e = e0; e < e1; e++) {
        int c = g_ccol[e];
        float v = g_cval[e];
        acc += v * Xin[(long)c * 256 + f];
    }
    if (relu) acc = fmaxf(acc, 0.f);
    if (split128) {
        if (f < 128) {
            out1[(long)r * 128 + f] = acc;
            bf16split(acc, bh[(long)r * 128 + f], bl[(long)r * 128 + f]);
        } else {
            out2[(long)r * 128 + f - 128] = acc;
        }
    } else {
        bf16split(acc, bh[(long)r * 256 + f], bl[(long)r * 256 + f]);
    }
}

// ---------------- tensor-core GEMM: C[M,N] = A[M,K] @ Bt[N,K]^T --------------
__global__ __launch_bounds__(256, 1) void gemm_mma_kernel(
    const __nv_bfloat16* __restrict__ Ahi, const __nv_bfloat16* __restrict__ Alo, int lda,
    const __nv_bfloat16* __restrict__ Bhi, const __nv_bfloat16* __restrict__ Blo, int ldb,
    const float* __restrict__ bias,
    float* __restrict__ Cf, __half* __restrict__ C16,
    __nv_bfloat16* __restrict__ Chi, __nv_bfloat16* __restrict__ Clo,
    int ldc, int M, int N, int K, int relu, long sB, long sC)
{
    Bhi += (long)blockIdx.z * sB;
    Blo += (long)blockIdx.z * sB;
    long coff = (long)blockIdx.z * sC;
    extern __shared__ char smem[];
    uint32_t sb = smem_to_u32(smem);

    int tid = threadIdx.x, lane = tid & 31, wid = tid >> 5;
    int m0 = blockIdx.y * 128, n0 = blockIdx.x * 128;

    int mw = (wid & 1) << 6;
    int nw = (wid >> 1) << 5;
    float acc[4][4][4];
#pragma unroll
    for (int a = 0; a < 4; a++)
#pragma unroll
        for (int b = 0; b < 4; b++)
#pragma unroll
            for (int c = 0; c < 4; c++) acc[a][b][c] = 0.f;

    int arow = mw + (lane & 15);
    uint32_t acol = ((uint32_t)(lane >> 4)) * 16u;
    int brow = nw + (lane & 7);
    uint32_t bcol = ((uint32_t)((lane >> 3) & 1)) * 16u;

    int r = tid >> 1, half = tid & 1;

    for (int k0 = 0; k0 < K; k0 += 128) {
        {
            const __nv_bfloat16* srcs[4] = {Ahi, Alo, Bhi, Blo};
            int lds[4]   = {lda, lda, ldb, ldb};
            int base[4]  = {m0, m0, n0, n0};
            int limit[4] = {M, M, N, N};
#pragma unroll
            for (int tI = 0; tI < 4; tI++) {
                long gr = (long)base[tI] + r;
                bool rv = gr < limit[tI];
                const __nv_bfloat16* sp = srcs[tI] + gr * (long)lds[tI] + k0 + half * 64;
                uint4* d = (uint4*)(smem + tI * SY_TILE_BYTES + r * SY_PITCH_B + half * 128);
#pragma unroll
                for (int c = 0; c < 8; c++) {
                    int col0 = half * 64 + c * 8;
                    uint4 v = make_uint4(0, 0, 0, 0);
                    if (rv && (k0 + col0 + 8) <= K) v = *(const uint4*)(sp + c * 8);
                    d[c] = v;
                }
            }
        }
        __syncthreads();

        int ksteps = (K - k0) >= 128 ? 8 : ((K - k0 + 15) >> 4);
        uint32_t offA_hi = 0, offA_lo = SY_TILE_BYTES;
        uint32_t offB_hi = 2u * SY_TILE_BYTES, offB_lo = 3u * SY_TILE_BYTES;
        for (int ks = 0; ks < ksteps; ks++) {
            uint32_t kb = (uint32_t)ks * 32u;
            uint32_t bh[4][2], bl[4][2];
#pragma unroll
            for (int nf = 0; nf < 4; nf++) {
                uint32_t ro = (uint32_t)(brow + nf * 8) * SY_PITCH_B + kb + bcol;
                LDSM_X2(bh[nf], sb + offB_hi + ro);
                LDSM_X2(bl[nf], sb + offB_lo + ro);
            }
#pragma unroll
            for (int mf = 0; mf < 4; mf++) {
                uint32_t ro = (uint32_t)(arow + mf * 16) * SY_PITCH_B + kb + acol;
                uint32_t ah[4], al[4];
                LDSM_X4(ah, sb + offA_hi + ro);
                LDSM_X4(al, sb + offA_lo + ro);
#pragma unroll
                for (int nf = 0; nf < 4; nf++) {
                    MMA_BF16(acc[mf][nf], ah, bh[nf]);
                    MMA_BF16(acc[mf][nf], ah, bl[nf]);
                    MMA_BF16(acc[mf][nf], al, bh[nf]);
                }
            }
        }
        __syncthreads();
    }

    // epilogue
    int mrow = lane >> 2, ncol = (lane & 3) * 2;
#pragma unroll
    for (int mf = 0; mf < 4; mf++) {
#pragma unroll
        for (int nf = 0; nf < 4; nf++) {
            long gm = m0 + mw + mf * 16 + mrow;
            int gn = n0 + nw + nf * 8 + ncol;
            float v0 = acc[mf][nf][0], v1 = acc[mf][nf][1];
            float v2 = acc[mf][nf][2], v3 = acc[mf][nf][3];
            if (bias) {
                float b0 = bias[gn], b1 = bias[gn + 1];
                v0 += b0; v1 += b1; v2 += b0; v3 += b1;
            }
            if (relu) {
                v0 = fmaxf(v0, 0.f); v1 = fmaxf(v1, 0.f);
                v2 = fmaxf(v2, 0.f); v3 = fmaxf(v3, 0.f);
            }
            if (gm < M) {
                long o = coff + gm * (long)ldc + gn;
                if (Cf) *(float2*)&Cf[o] = make_float2(v0, v1);
                if (C16) *(__half2*)&C16[o] = __floats2half2_rn(v0, v1);
                if (Chi) {
                    __nv_bfloat162 h, l;
                    bf16split(v0, h.x, l.x); bf16split(v1, h.y, l.y);
                    *(__nv_bfloat162*)&Chi[o] = h;
                    *(__nv_bfloat162*)&Clo[o] = l;
                }
            }
            if (gm + 8 < M) {
                long o = coff + (gm + 8) * (long)ldc + gn;
                if (Cf) *(float2*)&Cf[o] = make_float2(v2, v3);
                if (C16) *(__half2*)&C16[o] = __floats2half2_rn(v2, v3);
                if (Chi) {
                    __nv_bfloat162 h, l;
                    bf16split(v2, h.x, l.x); bf16split(v3, h.y, l.y);
                    *(__nv_bfloat162*)&Chi[o] = h;
                    *(__nv_bfloat162*)&Clo[o] = l;
                }
            }
        }
    }
}

// ---------------- SYRK via mma.sync bf16 hi/lo: C = Z Z^T --------------------
// Paired-j: one CTA handles tiles (i,j0) and (i,j0+1). Smem: 6 tiles.
__device__ __forceinline__ void ld_tile(char* smem, int off,
                                        const __nv_bfloat16* __restrict__ src,
                                        long row0, int r, int half) {
    long gr = row0 + r;
    uint4 v[8];
    if (gr < NTOT) {
        const uint4* s = reinterpret_cast<const uint4*>(src + gr * 128 + half * 64);
#pragma unroll
        for (int c = 0; c < 8; c++) v[c] = s[c];
    } else {
#pragma unroll
        for (int c = 0; c < 8; c++) v[c] = make_uint4(0, 0, 0, 0);
    }
    uint4* d = reinterpret_cast<uint4*>(smem + off + r * SY_PITCH_B + half * 128);
#pragma unroll
    for (int c = 0; c < 8; c++) d[c] = v[c];
}

__device__ __forceinline__ void syrk_tile(uint32_t sb, uint32_t offBh, uint32_t offBl,
                                          long i0, long j0, bool mirror,
                                          float* __restrict__ C, int lane, int wid) {
    int mw = (wid & 1) << 6;
    int nw = (wid >> 1) << 5;
    float acc[4][4][4];
#pragma unroll
    for (int a = 0; a < 4; a++)
#pragma unroll
        for (int b = 0; b < 4; b++)
#pragma unroll
            for (int c = 0; c < 4; c++) acc[a][b][c] = 0.f;

    int arow = mw + (lane & 15);
    uint32_t acol = ((uint32_t)(lane >> 4)) * 16u;
    int brow = nw + (lane & 7);
    uint32_t bcol = ((uint32_t)((lane >> 3) & 1)) * 16u;

#pragma unroll
    for (int ks = 0; ks < 8; ks++) {
        uint32_t kb = (uint32_t)ks * 32u;
        uint32_t bh[4][2], bl[4][2];
#pragma unroll
        for (int nf = 0; nf < 4; nf++) {
            uint32_t ro = (uint32_t)(brow + nf * 8) * SY_PITCH_B + kb + bcol;
            LDSM_X2(bh[nf], sb + offBh + ro);
            LDSM_X2(bl[nf], sb + offBl + ro);
        }
#pragma unroll
        for (int mf = 0; mf < 4; mf++) {
            uint32_t ro = (uint32_t)(arow + mf * 16) * SY_PITCH_B + kb + acol;
            uint32_t ah[4], al[4];
            LDSM_X4(ah, sb + 0 + ro);
            LDSM_X4(al, sb + SY_TILE_BYTES + ro);
#pragma unroll
            for (int nf = 0; nf < 4; nf++) {
                MMA_BF16(acc[mf][nf], ah, bh[nf]);
                MMA_BF16(acc[mf][nf], ah, bl[nf]);
                MMA_BF16(acc[mf][nf], al, bh[nf]);
            }
        }
    }

    int mrow = lane >> 2, ncol = (lane & 3) * 2;
#pragma unroll
    for (int mf = 0; mf < 4; mf++) {
#pragma unroll
        for (int nf = 0; nf < 4; nf++) {
            long gm = i0 + mw + mf * 16 + mrow;
            long gn = j0 + nw + nf * 8 + ncol;
            float v0 = acc[mf][nf][0], v1 = acc[mf][nf][1];
            float v2 = acc[mf][nf][2], v3 = acc[mf][nf][3];
            if (gn < NTOT) {
                if (gm < NTOT)
                    *(float2*)&C[gm * (long)NTOT + gn] = make_float2(v0, v1);
                if (gm + 8 < NTOT)
                    *(float2*)&C[(gm + 8) * (long)NTOT + gn] = make_float2(v2, v3);
            }
            if (mirror) {
                if (gn < NTOT) {
                    if (gm < NTOT)      C[gn * (long)NTOT + gm] = v0;
                    if (gm + 8 < NTOT)  C[gn * (long)NTOT + gm + 8] = v2;
                }
                if (gn + 1 < NTOT) {
                    if (gm < NTOT)      C[(gn + 1) * (long)NTOT + gm] = v1;
                    if (gm + 8 < NTOT)  C[(gn + 1) * (long)NTOT + gm + 8] = v3;
                }
            }
        }
    }
}

__global__ __launch_bounds__(256, 1) void syrk_mma_kernel(float* __restrict__ C) {
    extern __shared__ char smem[];
    int rem = blockIdx.x;
    int i = 0;
    while (true) {
        int np = (95 - i) >> 1;
        if (rem < np) break;
        rem -= np;
        i++;
    }
    int j0 = i + 2 * rem;
    int j1 = j0 + 1;
    bool has2 = (j1 <= 93);
    long i0 = (long)i * 128, jj0 = (long)j0 * 128, jj1 = (long)j1 * 128;

    int tid = threadIdx.x, lane = tid & 31, wid = tid >> 5;

    {
        int r = tid >> 1, half = tid & 1;
        ld_tile(smem, 0,                 g_Zhi, i0, r, half);
        ld_tile(smem, SY_TILE_BYTES,     g_Zlo, i0, r, half);
        ld_tile(smem, 2 * SY_TILE_BYTES, g_Zhi, jj0, r, half);
        ld_tile(smem, 3 * SY_TILE_BYTES, g_Zlo, jj0, r, half);
        if (has2) {
            ld_tile(smem, 4 * SY_TILE_BYTES, g_Zhi, jj1, r, half);
            ld_tile(smem, 5 * SY_TILE_BYTES, g_Zlo, jj1, r, half);
        }
    }
    __syncthreads();

    uint32_t sb = smem_to_u32(smem);
    syrk_tile(sb, 2u * SY_TILE_BYTES, 3u * SY_TILE_BYTES, i0, jj0, j0 != i, C, lane, wid);
    if (has2)
        syrk_tile(sb, 4u * SY_TILE_BYTES, 5u * SY_TILE_BYTES, i0, jj1, true, C, lane, wid);
}

// ---------------- host ----------------
extern "C" void kernel_launch(void* const* d_in, const int* in_sizes, int n_in,
                              void* d_out, int out_size) {
    const float* drug_x = (const float*)d_in[0];
    const int*   pro_x  = (const int*)d_in[1];
    const int*   arows  = (const int*)d_in[2];
    const int*   acols  = (const int*)d_in[3];
    const float* avals  = (const float*)d_in[4];
    const float* w1     = (const float*)d_in[5];
    const float* b1     = (const float*)d_in[6];
    const float* w2     = (const float*)d_in[7];
    const float* b2     = (const float*)d_in[8];
    const float* w3     = (const float*)d_in[9];
    const float* b3     = (const float*)d_in[10];
    const float* emb_xt = (const float*)d_in[11];
    const float* conv_w = (const float*)d_in[12];
    const float* conv_b = (const float*)d_in[13];
    const float* fc_w   = (const float*)d_in[14];
    const float* fc_b   = (const float*)d_in[15];
    const float* gc1_w  = (const float*)d_in[16];
    const float* gc2_w  = (const float*)d_in[17];
    const float* gc3_w  = (const float*)d_in[18];
    float* out = (float*)d_out;

    float *pXW1, *pHW;
    __half* pM16;
    int *pcnt;
    cudaGetSymbolAddress((void**)&pM16, g_M16);
    cudaGetSymbolAddress((void**)&pXW1, g_XW1);
    cudaGetSymbolAddress((void**)&pHW,  g_HW);
    cudaGetSymbolAddress((void**)&pcnt, g_cnt);
    __nv_bfloat16 *pdxh,*pdxl,*pd1h,*pd1l,*pd2h,*pd2l,*pXh,*pXl,*pH1h,*pH1l;
    __nv_bfloat16 *pw1h,*pw1l,*pw2h,*pw2l,*pw3h,*pw3l,*pg1h,*pg1l,*pg23h,*pg23l;
    __nv_bfloat16 *pW2h,*pW2l,*pGth,*pGtl,*pZh,*pZl;
    cudaGetSymbolAddress((void**)&pdxh, g_dxhi);  cudaGetSymbolAddress((void**)&pdxl, g_dxlo);
    cudaGetSymbolAddress((void**)&pd1h, g_d1hi);  cudaGetSymbolAddress((void**)&pd1l, g_d1lo);
    cudaGetSymbolAddress((void**)&pd2h, g_d2hi);  cudaGetSymbolAddress((void**)&pd2l, g_d2lo);
    cudaGetSymbolAddress((void**)&pXh,  g_Xhi);   cudaGetSymbolAddress((void**)&pXl,  g_Xlo);
    cudaGetSymbolAddress((void**)&pH1h, g_H1hi);  cudaGetSymbolAddress((void**)&pH1l, g_H1lo);
    cudaGetSymbolAddress((void**)&pw1h, g_w1thi); cudaGetSymbolAddress((void**)&pw1l, g_w1tlo);
    cudaGetSymbolAddress((void**)&pw2h, g_w2thi); cudaGetSymbolAddress((void**)&pw2l, g_w2tlo);
    cudaGetSymbolAddress((void**)&pw3h, g_w3thi); cudaGetSymbolAddress((void**)&pw3l, g_w3tlo);
    cudaGetSymbolAddress((void**)&pg1h, g_gc1thi);cudaGetSymbolAddress((void**)&pg1l, g_gc1tlo);
    cudaGetSymbolAddress((void**)&pg23h,g_gc23thi);cudaGetSymbolAddress((void**)&pg23l,g_gc23tlo);
    cudaGetSymbolAddress((void**)&pW2h, g_W2dhi); cudaGetSymbolAddress((void**)&pW2l, g_W2dlo);
    cudaGetSymbolAddress((void**)&pGth, g_Gtthi); cudaGetSymbolAddress((void**)&pGtl, g_Gttlo);
    cudaGetSymbolAddress((void**)&pZh,  g_Zhi);   cudaGetSymbolAddress((void**)&pZl,  g_Zlo);

    static int smem_set = 0;
    if (!smem_set) {
        cudaFuncSetAttribute(syrk_mma_kernel, cudaFuncAttributeMaxDynamicSharedMemorySize,
                             SY_SMEM_TOTAL);
        cudaFuncSetAttribute(gemm_mma_kernel, cudaFuncAttributeMaxDynamicSharedMemorySize,
                             GM_SMEM_TOTAL);
        smem_set = 1;
    }

    // CSR build
    cudaMemsetAsync(pcnt, 0, NTOT * sizeof(int));
    count_kernel<<<750, 256>>>(arows);
    scan_kernel<<<1, 1024>>>();
    scatter_kernel<<<750, 256>>>(arows, acols, avals);

    // merged prep (all splits/repacks/G/pbias)
    prep_kernel<<<PS8, 256>>>(drug_x, w1, w2, w3, gc1_w, gc2_w, gc3_w,
                              conv_w, emb_xt, fc_w, fc_b, conv_b);

    // drug MLP (tensor cores)
    gemm_mma_kernel<<<dim3(1, 86, 1), 256, GM_SMEM_TOTAL>>>(
        pdxh, pdxl, 176, pw1h, pw1l, 176, b1,
        nullptr, nullptr, pd1h, pd1l, 128, N_DRUG, 128, 176, 1, 0, 0);
    gemm_mma_kernel<<<dim3(2, 86, 1), 256, GM_SMEM_TOTAL>>>(
        pd1h, pd1l, 128, pw2h, pw2l, 128, b2,
        nullptr, nullptr, pd2h, pd2l, 256, N_DRUG, 256, 128, 1, 0, 0);
    gemm_mma_kernel<<<dim3(1, 86, 1), 256, GM_SMEM_TOTAL>>>(
        pd2h, pd2l, 256, pw3h, pw3l, 256, b3,
        nullptr, nullptr, pXh, pXl, 128, N_DRUG, 128, 256, 1, 0, 0);

    // protein: M[t] = W2d @ Gt[t]  (batched, tensor cores, fp16 output)
    gemm_mma_kernel<<<dim3(1, 8, 26), 256, GM_SMEM_TOTAL>>>(
        pW2h, pW2l, 256, pGth, pGtl, 256, nullptr,
        nullptr, pM16, nullptr, nullptr, 128, N_PRO, 128, 256, 0,
        128L * 256, (long)N_PRO * 128);
    protein_gather_kernel<<<1000, 128>>>(pro_x);

    // GCN encoder
    gemm_mma_kernel<<<dim3(2, 94, 1), 256, GM_SMEM_TOTAL>>>(
        pXh, pXl, 128, pg1h, pg1l, 128, nullptr,
        pXW1, nullptr, nullptr, nullptr, 256, NTOT, 256, 128, 0, 0, 0);
    spmm256_kernel<<<NTOT, 256>>>(pXW1, nullptr, nullptr, pH1h, pH1l, 1, 0);
    gemm_mma_kernel<<<dim3(2, 94, 1), 256, GM_SMEM_TOTAL>>>(
        pH1h, pH1l, 256, pg23h, pg23l, 256, nullptr,
        pHW, nullptr, nullptr, nullptr, 256, NTOT, 256, 256, 0, 0, 0);
    spmm256_kernel<<<NTOT, 256>>>(pHW, out + OFF_MU, out + OFF_LV, pZh, pZl, 0, 1);

    // decoder: adj_rec = Z Z^T (paired-j tiles)
    syrk_mma_kernel<<<2256, 256, SY_SMEM_TOTAL>>>(out);
}